// round 2
// baseline (speedup 1.0000x reference)
#include <cuda_runtime.h>

#define HW 4096
#define CC 256
#define BB 4

// ---- scratch (static device arrays; no allocation allowed) ----
__device__ float g_h [BB*CC*HW];   // groupnorm output, (b, c, s)
__device__ float g_q [BB*CC*HW];   // q conv output,    (b, c, s) -> raw view rows are contiguous
__device__ float g_kt[BB*HW*CC];   // k conv output transposed: (b, s, c)
__device__ float g_v [BB*CC*HW];   // v conv output,    (b, c, s)
__device__ float g_a [BB*HW*CC];   // attention output, (b, n, c)

// ============================================================
// GroupNorm: one block per (batch, group). 32 groups, 8 ch each.
// ============================================================
__global__ void gn_kernel(const float* __restrict__ x,
                          const float* __restrict__ gw,
                          const float* __restrict__ gb) {
    int b = blockIdx.x >> 5;
    int g = blockIdx.x & 31;
    const float* xp = x   + ((size_t)b*CC + g*8) * HW;
    float*       hp = g_h + ((size_t)b*CC + g*8) * HW;
    int tid = threadIdx.x;

    float s = 0.f, ss = 0.f;
    for (int i = tid; i < 8*HW; i += 256) {
        float v = xp[i];
        s += v; ss += v*v;
    }
    __shared__ float red0[8], red1[8];
    #pragma unroll
    for (int off = 16; off; off >>= 1) {
        s  += __shfl_xor_sync(0xffffffffu, s,  off);
        ss += __shfl_xor_sync(0xffffffffu, ss, off);
    }
    if ((tid & 31) == 0) { red0[tid>>5] = s; red1[tid>>5] = ss; }
    __syncthreads();
    __shared__ float mu_s, rstd_s;
    if (tid == 0) {
        float S = 0.f, SS = 0.f;
        #pragma unroll
        for (int i = 0; i < 8; i++) { S += red0[i]; SS += red1[i]; }
        float inv = 1.0f / (8.0f*HW);
        float mu = S * inv;
        float var = SS * inv - mu*mu;
        mu_s = mu;
        rstd_s = rsqrtf(var + 1e-5f);
    }
    __syncthreads();
    float mu = mu_s, rstd = rstd_s;
    for (int i = tid; i < 8*HW; i += 256) {
        int c = g*8 + (i >> 12);
        hp[i] = (xp[i] - mu) * rstd * gw[c] + gb[c];
    }
}

// ============================================================
// 1x1 conv projection: out[o,s] = sum_c W[o,c] * H[c,s] + bias[o]
// WHICH = 0 -> g_q (o-major), 1 -> g_kt (s-major / transposed), 2 -> g_v
// 64x64 tile, 256 threads, 4x4 microtile, K-tile 16.
// ============================================================
template<int WHICH>
__global__ void proj_kernel(const float* __restrict__ Wm,
                            const float* __restrict__ bias) {
    int b  = blockIdx.z;
    int o0 = blockIdx.y << 6;
    int s0 = blockIdx.x << 6;
    const float* Hb = g_h + (size_t)b*CC*HW;

    __shared__ float Ws[16][65];  // [k][o] padded
    __shared__ float Hs[16][64];  // [k][s]

    int tid = threadIdx.x;
    int tx = tid & 15, ty = tid >> 4;
    float acc[4][4] = {};

    for (int k0 = 0; k0 < CC; k0 += 16) {
        // W tile: (o0+i, k0+j)
        for (int l = tid; l < 1024; l += 256) {
            int i = l >> 4, j = l & 15;
            Ws[j][i] = Wm[(o0+i)*CC + k0 + j];
        }
        // H tile: (k0+j, s0+i)
        for (int l = tid; l < 1024; l += 256) {
            int j = l >> 6, i = l & 63;
            Hs[j][i] = Hb[(size_t)(k0+j)*HW + s0 + i];
        }
        __syncthreads();
        #pragma unroll
        for (int j = 0; j < 16; j++) {
            float wr[4], hr[4];
            if (WHICH == 1) {
                #pragma unroll
                for (int u = 0; u < 4; u++) wr[u] = Ws[j][tx*4+u];
                #pragma unroll
                for (int u = 0; u < 4; u++) hr[u] = Hs[j][ty*4+u];
                #pragma unroll
                for (int u = 0; u < 4; u++)
                    #pragma unroll
                    for (int v = 0; v < 4; v++)
                        acc[u][v] += hr[u] * wr[v];      // u->s, v->o
            } else {
                #pragma unroll
                for (int u = 0; u < 4; u++) wr[u] = Ws[j][ty*4+u];
                #pragma unroll
                for (int u = 0; u < 4; u++) hr[u] = Hs[j][tx*4+u];
                #pragma unroll
                for (int u = 0; u < 4; u++)
                    #pragma unroll
                    for (int v = 0; v < 4; v++)
                        acc[u][v] += wr[u] * hr[v];      // u->o, v->s
            }
        }
        __syncthreads();
    }

    if (WHICH == 1) {
        float* ob = g_kt + (size_t)b*HW*CC;
        #pragma unroll
        for (int u = 0; u < 4; u++) {
            int s = s0 + ty*4 + u;
            int o = o0 + tx*4;
            float4 r = make_float4(acc[u][0]+bias[o],   acc[u][1]+bias[o+1],
                                   acc[u][2]+bias[o+2], acc[u][3]+bias[o+3]);
            *reinterpret_cast<float4*>(&ob[(size_t)s*CC + o]) = r;
        }
    } else {
        float* ob = (WHICH == 0 ? g_q : g_v) + (size_t)b*CC*HW;
        #pragma unroll
        for (int u = 0; u < 4; u++) {
            int o = o0 + ty*4 + u;
            float bv = bias[o];
            float4 r = make_float4(acc[u][0]+bv, acc[u][1]+bv,
                                   acc[u][2]+bv, acc[u][3]+bv);
            *reinterpret_cast<float4*>(&ob[(size_t)o*HW + s0 + tx*4]) = r;
        }
    }
}

// ============================================================
// Flash attention, fp32 SIMT.
// Per block: 64 query rows (raw-view rows = contiguous 256-float chunks).
// Stream over 64 key tiles of 64 rows each; online softmax.
// smem: Q/K/V 64x(stride 257), P 64x(stride 65) -> ~209 KB dynamic.
// ============================================================
#define QSTR 257
#define PSTR 65

__global__ void __launch_bounds__(256, 1) attn_kernel() {
    int b  = blockIdx.y;
    int n0 = blockIdx.x << 6;
    const float* qf = g_q  + (size_t)b*CC*HW;
    const float* kf = g_kt + (size_t)b*HW*CC;
    const float* vf = g_v  + (size_t)b*CC*HW;

    extern __shared__ float sm[];
    float* Qs = sm;                    // 64*257
    float* Ks = Qs + 64*QSTR;          // 64*257
    float* Vs = Ks + 64*QSTR;          // 64*257
    float* Ps = Vs + 64*QSTR;          // 64*65

    int tid = threadIdx.x;
    int tx = tid & 15, ty = tid >> 4;

    // load Q tile (scaled by C^-0.5 = 1/16)
    {
        const float scale = 0.0625f;
        const float4* src = reinterpret_cast<const float4*>(qf + (size_t)n0*CC);
        for (int l = tid; l < 4096; l += 256) {
            float4 v = src[l];
            int row = l >> 6, c = (l & 63) << 2;
            float* d = &Qs[row*QSTR + c];
            d[0] = v.x*scale; d[1] = v.y*scale; d[2] = v.z*scale; d[3] = v.w*scale;
        }
    }

    float m_r[4], l_r[4], o_acc[4][16];
    #pragma unroll
    for (int u = 0; u < 4; u++) {
        m_r[u] = -1e30f; l_r[u] = 0.f;
        #pragma unroll
        for (int j = 0; j < 16; j++) o_acc[u][j] = 0.f;
    }

    for (int m0 = 0; m0 < HW; m0 += 64) {
        __syncthreads();   // protect K/V/P from previous-iteration readers
        {
            const float4* ks = reinterpret_cast<const float4*>(kf + (size_t)m0*CC);
            const float4* vs = reinterpret_cast<const float4*>(vf + (size_t)m0*CC);
            for (int l = tid; l < 4096; l += 256) {
                int row = l >> 6, c = (l & 63) << 2;
                float4 kv = ks[l];
                float4 vv = vs[l];
                float* kd = &Ks[row*QSTR + c];
                kd[0]=kv.x; kd[1]=kv.y; kd[2]=kv.z; kd[3]=kv.w;
                float* vd = &Vs[row*QSTR + c];
                vd[0]=vv.x; vd[1]=vv.y; vd[2]=vv.z; vd[3]=vv.w;
            }
        }
        __syncthreads();

        // S tile: 64x64, thread computes rows ty*4+u, cols tx*4+v
        float s_t[4][4] = {};
        #pragma unroll 4
        for (int c = 0; c < CC; c++) {
            float qr[4], kr[4];
            #pragma unroll
            for (int u = 0; u < 4; u++) qr[u] = Qs[(ty*4+u)*QSTR + c];
            #pragma unroll
            for (int v = 0; v < 4; v++) kr[v] = Ks[(tx*4+v)*QSTR + c];
            #pragma unroll
            for (int u = 0; u < 4; u++)
                #pragma unroll
                for (int v = 0; v < 4; v++)
                    s_t[u][v] += qr[u] * kr[v];
        }

        // online softmax per row (reduce across the 16 tx lanes)
        #pragma unroll
        for (int u = 0; u < 4; u++) {
            float mx = fmaxf(fmaxf(s_t[u][0], s_t[u][1]), fmaxf(s_t[u][2], s_t[u][3]));
            #pragma unroll
            for (int off = 8; off; off >>= 1)
                mx = fmaxf(mx, __shfl_xor_sync(0xffffffffu, mx, off));
            float mn = fmaxf(m_r[u], mx);
            float alpha = __expf(m_r[u] - mn);
            float p[4], rs = 0.f;
            #pragma unroll
            for (int v = 0; v < 4; v++) { p[v] = __expf(s_t[u][v] - mn); rs += p[v]; }
            #pragma unroll
            for (int off = 8; off; off >>= 1)
                rs += __shfl_xor_sync(0xffffffffu, rs, off);
            l_r[u] = l_r[u]*alpha + rs;
            m_r[u] = mn;
            #pragma unroll
            for (int v = 0; v < 4; v++) Ps[(ty*4+u)*PSTR + tx*4 + v] = p[v];
            #pragma unroll
            for (int j = 0; j < 16; j++) o_acc[u][j] *= alpha;
        }
        __syncthreads();

        // O += P @ V  (thread owns rows ty*4+u, cols tx + 16*j)
        #pragma unroll 2
        for (int mm = 0; mm < 64; mm++) {
            float pv[4];
            #pragma unroll
            for (int u = 0; u < 4; u++) pv[u] = Ps[(ty*4+u)*PSTR + mm];
            #pragma unroll
            for (int j = 0; j < 16; j++) {
                float vv = Vs[mm*QSTR + tx + (j << 4)];
                #pragma unroll
                for (int u = 0; u < 4; u++) o_acc[u][j] += pv[u] * vv;
            }
        }
    }

    // epilogue: normalize + write (b, n, c)
    float* ab = g_a + (size_t)b*HW*CC;
    #pragma unroll
    for (int u = 0; u < 4; u++) {
        float inv = 1.0f / l_r[u];
        size_t base = (size_t)(n0 + ty*4 + u) * CC;
        #pragma unroll
        for (int j = 0; j < 16; j++)
            ab[base + tx + (j << 4)] = o_acc[u][j] * inv;
    }
}

// ============================================================
// Output projection + residual:
// out[b,o,s] = x[b,o,s] + bp[o] + sum_c wp[o,c] * A[b,s,c]
// ============================================================
__global__ void outproj_kernel(const float* __restrict__ Wm,
                               const float* __restrict__ bias,
                               const float* __restrict__ x,
                               float* __restrict__ outp) {
    int b  = blockIdx.z;
    int o0 = blockIdx.y << 6;
    int s0 = blockIdx.x << 6;
    const float* Ab = g_a + (size_t)b*HW*CC;

    __shared__ float Ws[16][65];  // [k][o]
    __shared__ float As[16][65];  // [k][s]

    int tid = threadIdx.x;
    int tx = tid & 15, ty = tid >> 4;
    float acc[4][4] = {};

    for (int k0 = 0; k0 < CC; k0 += 16) {
        for (int l = tid; l < 1024; l += 256) {
            int i = l >> 4, j = l & 15;
            Ws[j][i] = Wm[(o0+i)*CC + k0 + j];
        }
        for (int l = tid; l < 1024; l += 256) {
            int i = l >> 4, j = l & 15;
            As[j][i] = Ab[(size_t)(s0+i)*CC + k0 + j];
        }
        __syncthreads();
        #pragma unroll
        for (int j = 0; j < 16; j++) {
            float wr[4], ar[4];
            #pragma unroll
            for (int u = 0; u < 4; u++) wr[u] = Ws[j][ty*4+u];
            #pragma unroll
            for (int v = 0; v < 4; v++) ar[v] = As[j][tx*4+v];
            #pragma unroll
            for (int u = 0; u < 4; u++)
                #pragma unroll
                for (int v = 0; v < 4; v++)
                    acc[u][v] += wr[u] * ar[v];
        }
        __syncthreads();
    }

    const float* xb = x + (size_t)b*CC*HW;
    float* ob = outp + (size_t)b*CC*HW;
    #pragma unroll
    for (int u = 0; u < 4; u++) {
        int o = o0 + ty*4 + u;
        float bv = bias[o];
        size_t idx = (size_t)o*HW + s0 + tx*4;
        float4 xv = *reinterpret_cast<const float4*>(&xb[idx]);
        float4 r = make_float4(acc[u][0]+bv+xv.x, acc[u][1]+bv+xv.y,
                               acc[u][2]+bv+xv.z, acc[u][3]+bv+xv.w);
        *reinterpret_cast<float4*>(&ob[idx]) = r;
    }
}

// ============================================================
extern "C" void kernel_launch(void* const* d_in, const int* in_sizes, int n_in,
                              void* d_out, int out_size) {
    const float* x    = (const float*)d_in[0];
    const float* gn_w = (const float*)d_in[1];
    const float* gn_b = (const float*)d_in[2];
    const float* wq   = (const float*)d_in[3];
    const float* bq   = (const float*)d_in[4];
    const float* wk   = (const float*)d_in[5];
    const float* bk   = (const float*)d_in[6];
    const float* wv   = (const float*)d_in[7];
    const float* bv   = (const float*)d_in[8];
    const float* wp   = (const float*)d_in[9];
    const float* bp   = (const float*)d_in[10];
    float* out = (float*)d_out;

    const int attn_smem = (3*64*QSTR + 64*PSTR) * (int)sizeof(float); // ~214 KB
    cudaFuncSetAttribute(attn_kernel, cudaFuncAttributeMaxDynamicSharedMemorySize, attn_smem);

    gn_kernel<<<128, 256>>>(x, gn_w, gn_b);

    dim3 pg(64, 4, BB);
    proj_kernel<0><<<pg, 256>>>(wq, bq);
    proj_kernel<1><<<pg, 256>>>(wk, bk);
    proj_kernel<2><<<pg, 256>>>(wv, bv);

    dim3 ag(64, BB);
    attn_kernel<<<ag, 256, attn_smem>>>();

    outproj_kernel<<<pg, 256>>>(wp, bp, x, out);
}

// round 3
// speedup vs baseline: 4.2406x; 4.2406x over previous
#include <cuda_runtime.h>
#include <cuda_bf16.h>
#include <cstdint>

#define HW 4096
#define CC 256
#define BB 4

// ---- scratch (static device arrays; no allocation allowed) ----
__device__ float g_h [BB*CC*HW];                              // groupnorm out, (b, c, s) fp32
__device__ __align__(16) __nv_bfloat16 g_q [BB*CC*HW];        // q  (b, c, s), pre-scaled by C^-0.5
__device__ __align__(16) __nv_bfloat16 g_kt[BB*HW*CC];        // k  transposed: (b, m, c)
__device__ __align__(16) __nv_bfloat16 g_v [BB*CC*HW];        // v  (b, c, s)
__device__ float g_a [BB*HW*CC];                              // attention out, (b, n, c) fp32

// ============================================================
// GroupNorm: one block per (batch, group). 32 groups, 8 ch each.
// ============================================================
__global__ void gn_kernel(const float* __restrict__ x,
                          const float* __restrict__ gw,
                          const float* __restrict__ gb) {
    int b = blockIdx.x >> 5;
    int g = blockIdx.x & 31;
    const float* xp = x   + ((size_t)b*CC + g*8) * HW;
    float*       hp = g_h + ((size_t)b*CC + g*8) * HW;
    int tid = threadIdx.x;

    float s = 0.f, ss = 0.f;
    for (int i = tid; i < 8*HW; i += 256) {
        float v = xp[i];
        s += v; ss += v*v;
    }
    __shared__ float red0[8], red1[8];
    #pragma unroll
    for (int off = 16; off; off >>= 1) {
        s  += __shfl_xor_sync(0xffffffffu, s,  off);
        ss += __shfl_xor_sync(0xffffffffu, ss, off);
    }
    if ((tid & 31) == 0) { red0[tid>>5] = s; red1[tid>>5] = ss; }
    __syncthreads();
    __shared__ float mu_s, rstd_s;
    if (tid == 0) {
        float S = 0.f, SS = 0.f;
        #pragma unroll
        for (int i = 0; i < 8; i++) { S += red0[i]; SS += red1[i]; }
        float inv = 1.0f / (8.0f*HW);
        float mu = S * inv;
        float var = SS * inv - mu*mu;
        mu_s = mu;
        rstd_s = rsqrtf(var + 1e-5f);
    }
    __syncthreads();
    float mu = mu_s, rstd = rstd_s;
    for (int i = tid; i < 8*HW; i += 256) {
        int c = g*8 + (i >> 12);
        hp[i] = (xp[i] - mu) * rstd * gw[c] + gb[c];
    }
}

// ---- bf16 pack helper ----
__device__ __forceinline__ uint32_t pk2(float a, float b) {
    __nv_bfloat162 t = __floats2bfloat162_rn(a, b);   // .x (low) = a
    return *reinterpret_cast<uint32_t*>(&t);
}

// ============================================================
// 1x1 conv projection (fp32 compute, bf16 output):
// out[o,s] = sum_c W[o,c] * H[c,s] + bias[o]
// WHICH = 0 -> g_q (o-major, scaled by 1/16), 1 -> g_kt (s-major), 2 -> g_v
// ============================================================
template<int WHICH>
__global__ void proj_kernel(const float* __restrict__ Wm,
                            const float* __restrict__ bias) {
    int b  = blockIdx.z;
    int o0 = blockIdx.y << 6;
    int s0 = blockIdx.x << 6;
    const float* Hb = g_h + (size_t)b*CC*HW;

    __shared__ float Ws[16][65];  // [k][o] padded
    __shared__ float Hs[16][64];  // [k][s]

    int tid = threadIdx.x;
    int tx = tid & 15, ty = tid >> 4;
    float acc[4][4] = {};

    for (int k0 = 0; k0 < CC; k0 += 16) {
        for (int l = tid; l < 1024; l += 256) {
            int i = l >> 4, j = l & 15;
            Ws[j][i] = Wm[(o0+i)*CC + k0 + j];
        }
        for (int l = tid; l < 1024; l += 256) {
            int j = l >> 6, i = l & 63;
            Hs[j][i] = Hb[(size_t)(k0+j)*HW + s0 + i];
        }
        __syncthreads();
        #pragma unroll
        for (int j = 0; j < 16; j++) {
            float wr[4], hr[4];
            if (WHICH == 1) {
                #pragma unroll
                for (int u = 0; u < 4; u++) wr[u] = Ws[j][tx*4+u];
                #pragma unroll
                for (int u = 0; u < 4; u++) hr[u] = Hs[j][ty*4+u];
                #pragma unroll
                for (int u = 0; u < 4; u++)
                    #pragma unroll
                    for (int v = 0; v < 4; v++)
                        acc[u][v] += hr[u] * wr[v];      // u->s, v->o
            } else {
                #pragma unroll
                for (int u = 0; u < 4; u++) wr[u] = Ws[j][ty*4+u];
                #pragma unroll
                for (int u = 0; u < 4; u++) hr[u] = Hs[j][tx*4+u];
                #pragma unroll
                for (int u = 0; u < 4; u++)
                    #pragma unroll
                    for (int v = 0; v < 4; v++)
                        acc[u][v] += wr[u] * hr[v];      // u->o, v->s
            }
        }
        __syncthreads();
    }

    if (WHICH == 1) {
        __nv_bfloat16* ob = g_kt + (size_t)b*HW*CC;
        #pragma unroll
        for (int u = 0; u < 4; u++) {
            int s = s0 + ty*4 + u;
            int o = o0 + tx*4;
            uint2 r;
            r.x = pk2(acc[u][0]+bias[o],   acc[u][1]+bias[o+1]);
            r.y = pk2(acc[u][2]+bias[o+2], acc[u][3]+bias[o+3]);
            *reinterpret_cast<uint2*>(&ob[(size_t)s*CC + o]) = r;
        }
    } else {
        const float scale = (WHICH == 0) ? 0.0625f : 1.0f;  // C^-0.5 folded into q
        __nv_bfloat16* ob = (WHICH == 0 ? g_q : g_v) + (size_t)b*CC*HW;
        #pragma unroll
        for (int u = 0; u < 4; u++) {
            int o = o0 + ty*4 + u;
            float bv = bias[o];
            uint2 r;
            r.x = pk2((acc[u][0]+bv)*scale, (acc[u][1]+bv)*scale);
            r.y = pk2((acc[u][2]+bv)*scale, (acc[u][3]+bv)*scale);
            *reinterpret_cast<uint2*>(&ob[(size_t)o*HW + s0 + tx*4]) = r;
        }
    }
}

// ============================================================
// Flash attention, bf16 tensor cores (mma.sync m16n8k16).
// 256 threads = 8 warps. Br=128 (16 rows/warp), Bc=64, d=256.
// Q/K/V raw-view rows are contiguous 256-bf16 chunks of the conv buffers.
// ============================================================
#define ASTR 264   // smem row stride in bf16 elements (conflict-free)

__device__ __forceinline__ uint32_t s2u(const void* p) {
    uint32_t a;
    asm("{ .reg .u64 t; cvta.to.shared.u64 t, %1; cvt.u32.u64 %0, t; }" : "=r"(a) : "l"(p));
    return a;
}
__device__ __forceinline__ void ldm4(uint32_t& r0, uint32_t& r1, uint32_t& r2, uint32_t& r3, uint32_t a) {
    asm volatile("ldmatrix.sync.aligned.m8n8.x4.shared.b16 {%0,%1,%2,%3},[%4];"
                 : "=r"(r0), "=r"(r1), "=r"(r2), "=r"(r3) : "r"(a));
}
__device__ __forceinline__ void ldm4t(uint32_t& r0, uint32_t& r1, uint32_t& r2, uint32_t& r3, uint32_t a) {
    asm volatile("ldmatrix.sync.aligned.m8n8.x4.trans.shared.b16 {%0,%1,%2,%3},[%4];"
                 : "=r"(r0), "=r"(r1), "=r"(r2), "=r"(r3) : "r"(a));
}
__device__ __forceinline__ void mma16816(float* d, uint32_t a0, uint32_t a1, uint32_t a2, uint32_t a3,
                                         uint32_t b0, uint32_t b1) {
    asm volatile("mma.sync.aligned.m16n8k16.row.col.f32.bf16.bf16.f32 "
                 "{%0,%1,%2,%3},{%4,%5,%6,%7},{%8,%9},{%0,%1,%2,%3};"
                 : "+f"(d[0]), "+f"(d[1]), "+f"(d[2]), "+f"(d[3])
                 : "r"(a0), "r"(a1), "r"(a2), "r"(a3), "r"(b0), "r"(b1));
}
__device__ __forceinline__ uint32_t cvt2(float hi, float lo) {
    uint32_t d; asm("cvt.rn.bf16x2.f32 %0, %1, %2;" : "=r"(d) : "f"(hi), "f"(lo)); return d;
}

__global__ void __launch_bounds__(256, 1) attn_kernel() {
    int b  = blockIdx.y;
    int n0 = blockIdx.x << 7;                          // 128 query rows per CTA
    const __nv_bfloat16* qf = g_q  + (size_t)b*CC*HW;  // raw flat view
    const __nv_bfloat16* kf = g_kt + (size_t)b*HW*CC;  // (m, c)
    const __nv_bfloat16* vf = g_v  + (size_t)b*CC*HW;  // raw flat view

    extern __shared__ __nv_bfloat16 sm[];
    __nv_bfloat16* Qs = sm;               // 128 x ASTR
    __nv_bfloat16* Ks = Qs + 128*ASTR;    //  64 x ASTR
    __nv_bfloat16* Vs = Ks + 64*ASTR;     //  64 x ASTR

    int tid  = threadIdx.x;
    int lane = tid & 31, warp = tid >> 5;
    int r0 = warp << 4;                   // 16 query rows per warp

    // load Q tile (contiguous 64KB)
    {
        const uint4* src = reinterpret_cast<const uint4*>(qf + (size_t)n0*CC);
        for (int l = tid; l < 4096; l += 256) {
            int row = l >> 5, col = (l & 31) << 3;
            *reinterpret_cast<uint4*>(&Qs[row*ASTR + col]) = src[l];
        }
    }

    uint32_t Qsa = s2u(Qs), Ksa = s2u(Ks), Vsa = s2u(Vs);
    int l8 = lane & 7;
    // A (Q) ldmatrix.x4: tiles [rows r..r+7 | r+8..r+15] x [k0..7 | k8..15]
    uint32_t a_base = Qsa + ((r0 + l8 + ((lane >> 3) & 1)*8)*ASTR + (lane >> 4)*8) * 2;
    // B (K) ldmatrix.x4: per n16 group g: rows 16g.. with [n8 tile | +8] x [k0 | k8]
    uint32_t kb_base = Ksa + ((((lane >> 4) & 1)*8 + l8)*ASTR + ((lane >> 3) & 1)*8) * 2;
    // B (V) ldmatrix.x4.trans: per kstep rows km..km+15, per n16 group cols 16g..
    uint32_t vb_base = Vsa + ((((lane >> 3) & 1)*8 + l8)*ASTR + (lane >> 4)*8) * 2;

    float s[8][4];
    float o[32][4];
    #pragma unroll
    for (int j = 0; j < 32; j++) { o[j][0]=o[j][1]=o[j][2]=o[j][3]=0.f; }
    float mrow[2] = {-1e30f, -1e30f};
    float lrow[2] = {0.f, 0.f};

    for (int m0 = 0; m0 < HW; m0 += 64) {
        __syncthreads();   // previous tile fully consumed
        {
            const uint4* ks = reinterpret_cast<const uint4*>(kf + (size_t)m0*CC);
            const uint4* vs = reinterpret_cast<const uint4*>(vf + (size_t)m0*CC);
            for (int l = tid; l < 2048; l += 256) {
                int row = l >> 5, col = (l & 31) << 3;
                *reinterpret_cast<uint4*>(&Ks[row*ASTR + col]) = ks[l];
                *reinterpret_cast<uint4*>(&Vs[row*ASTR + col]) = vs[l];
            }
        }
        __syncthreads();

        // ---- S = Q @ K^T (16 x 64 per warp) ----
        #pragma unroll
        for (int j = 0; j < 8; j++) { s[j][0]=s[j][1]=s[j][2]=s[j][3]=0.f; }

        #pragma unroll 4
        for (int kk = 0; kk < 16; kk++) {
            uint32_t a0,a1,a2,a3;
            ldm4(a0,a1,a2,a3, a_base + kk*32);
            #pragma unroll
            for (int g = 0; g < 4; g++) {
                uint32_t b00,b01,b10,b11;
                ldm4(b00,b01,b10,b11, kb_base + (uint32_t)(g*16*ASTR)*2 + kk*32);
                mma16816(s[2*g],   a0,a1,a2,a3, b00,b01);
                mma16816(s[2*g+1], a0,a1,a2,a3, b10,b11);
            }
        }

        // ---- online softmax (rows r=t/4 and r+8) ----
        float alpha[2];
        #pragma unroll
        for (int h = 0; h < 2; h++) {
            float mx = -1e30f;
            #pragma unroll
            for (int j = 0; j < 8; j++) mx = fmaxf(mx, fmaxf(s[j][2*h], s[j][2*h+1]));
            mx = fmaxf(mx, __shfl_xor_sync(0xffffffffu, mx, 1));
            mx = fmaxf(mx, __shfl_xor_sync(0xffffffffu, mx, 2));
            float mn = fmaxf(mrow[h], mx);
            float al = __expf(mrow[h] - mn);
            mrow[h] = mn;
            float rs = 0.f;
            #pragma unroll
            for (int j = 0; j < 8; j++) {
                float p0 = __expf(s[j][2*h]   - mn);
                float p1 = __expf(s[j][2*h+1] - mn);
                s[j][2*h] = p0; s[j][2*h+1] = p1;
                rs += p0 + p1;
            }
            rs += __shfl_xor_sync(0xffffffffu, rs, 1);
            rs += __shfl_xor_sync(0xffffffffu, rs, 2);
            lrow[h] = lrow[h]*al + rs;
            alpha[h] = al;
        }
        #pragma unroll
        for (int j = 0; j < 32; j++) {
            o[j][0] *= alpha[0]; o[j][1] *= alpha[0];
            o[j][2] *= alpha[1]; o[j][3] *= alpha[1];
        }

        // ---- O += P @ V (P from S fragments, no smem round-trip) ----
        #pragma unroll
        for (int ks = 0; ks < 4; ks++) {
            uint32_t a0 = cvt2(s[2*ks][1],   s[2*ks][0]);
            uint32_t a1 = cvt2(s[2*ks][3],   s[2*ks][2]);
            uint32_t a2 = cvt2(s[2*ks+1][1], s[2*ks+1][0]);
            uint32_t a3 = cvt2(s[2*ks+1][3], s[2*ks+1][2]);
            #pragma unroll
            for (int g = 0; g < 16; g++) {
                uint32_t b00,b01,b10,b11;
                ldm4t(b00,b01,b10,b11, vb_base + (uint32_t)(ks*16*ASTR + g*16)*2);
                mma16816(o[2*g],   a0,a1,a2,a3, b00,b01);
                mma16816(o[2*g+1], a0,a1,a2,a3, b10,b11);
            }
        }
    }

    // ---- epilogue: normalize, write g_a (n, c) fp32 ----
    float* ab = g_a + (size_t)b*HW*CC;
    int qr = lane >> 2, qc = (lane & 3) << 1;
    #pragma unroll
    for (int h = 0; h < 2; h++) {
        float inv = 1.0f / lrow[h];
        int row = n0 + r0 + qr + 8*h;
        #pragma unroll
        for (int j = 0; j < 32; j++) {
            float2 v = make_float2(o[j][2*h]*inv, o[j][2*h+1]*inv);
            *reinterpret_cast<float2*>(&ab[(size_t)row*CC + 8*j + qc]) = v;
        }
    }
}

// ============================================================
// Output projection + residual:
// out[b,o,s] = x[b,o,s] + bp[o] + sum_c wp[o,c] * A[b,s,c]
// ============================================================
__global__ void outproj_kernel(const float* __restrict__ Wm,
                               const float* __restrict__ bias,
                               const float* __restrict__ x,
                               float* __restrict__ outp) {
    int b  = blockIdx.z;
    int o0 = blockIdx.y << 6;
    int s0 = blockIdx.x << 6;
    const float* Ab = g_a + (size_t)b*HW*CC;

    __shared__ float Ws[16][65];
    __shared__ float As[16][65];

    int tid = threadIdx.x;
    int tx = tid & 15, ty = tid >> 4;
    float acc[4][4] = {};

    for (int k0 = 0; k0 < CC; k0 += 16) {
        for (int l = tid; l < 1024; l += 256) {
            int i = l >> 4, j = l & 15;
            Ws[j][i] = Wm[(o0+i)*CC + k0 + j];
        }
        for (int l = tid; l < 1024; l += 256) {
            int i = l >> 4, j = l & 15;
            As[j][i] = Ab[(size_t)(s0+i)*CC + k0 + j];
        }
        __syncthreads();
        #pragma unroll
        for (int j = 0; j < 16; j++) {
            float wr[4], ar[4];
            #pragma unroll
            for (int u = 0; u < 4; u++) wr[u] = Ws[j][ty*4+u];
            #pragma unroll
            for (int v = 0; v < 4; v++) ar[v] = As[j][tx*4+v];
            #pragma unroll
            for (int u = 0; u < 4; u++)
                #pragma unroll
                for (int v = 0; v < 4; v++)
                    acc[u][v] += wr[u] * ar[v];
        }
        __syncthreads();
    }

    const float* xb = x + (size_t)b*CC*HW;
    float* ob = outp + (size_t)b*CC*HW;
    #pragma unroll
    for (int u = 0; u < 4; u++) {
        int o = o0 + ty*4 + u;
        float bv = bias[o];
        size_t idx = (size_t)o*HW + s0 + tx*4;
        float4 xv = *reinterpret_cast<const float4*>(&xb[idx]);
        float4 r = make_float4(acc[u][0]+bv+xv.x, acc[u][1]+bv+xv.y,
                               acc[u][2]+bv+xv.z, acc[u][3]+bv+xv.w);
        *reinterpret_cast<float4*>(&ob[idx]) = r;
    }
}

// ============================================================
extern "C" void kernel_launch(void* const* d_in, const int* in_sizes, int n_in,
                              void* d_out, int out_size) {
    const float* x    = (const float*)d_in[0];
    const float* gn_w = (const float*)d_in[1];
    const float* gn_b = (const float*)d_in[2];
    const float* wq   = (const float*)d_in[3];
    const float* bq   = (const float*)d_in[4];
    const float* wk   = (const float*)d_in[5];
    const float* bk   = (const float*)d_in[6];
    const float* wv   = (const float*)d_in[7];
    const float* bv   = (const float*)d_in[8];
    const float* wp   = (const float*)d_in[9];
    const float* bp   = (const float*)d_in[10];
    float* out = (float*)d_out;

    const int attn_smem = 256 * ASTR * 2;  // (128+64+64) rows x 264 bf16 = 132 KB
    cudaFuncSetAttribute(attn_kernel, cudaFuncAttributeMaxDynamicSharedMemorySize, attn_smem);

    gn_kernel<<<128, 256>>>(x, gn_w, gn_b);

    dim3 pg(64, 4, BB);
    proj_kernel<0><<<pg, 256>>>(wq, bq);
    proj_kernel<1><<<pg, 256>>>(wk, bk);
    proj_kernel<2><<<pg, 256>>>(wv, bv);

    dim3 ag(32, BB);
    attn_kernel<<<ag, 256, attn_smem>>>();

    outproj_kernel<<<pg, 256>>>(wp, bp, x, out);
}

// round 4
// speedup vs baseline: 8.7161x; 2.0554x over previous
#include <cuda_runtime.h>
#include <cuda_bf16.h>
#include <cstdint>

#define HW 4096
#define CC 256
#define BB 4

// ---- scratch (static device arrays; no allocation allowed) ----
__device__ __align__(16) __nv_bfloat16 g_h [BB*CC*HW];   // groupnorm out, (b, c, s)
__device__ __align__(16) __nv_bfloat16 g_q [BB*CC*HW];   // q (b, c, s), pre-scaled by C^-0.5
__device__ __align__(16) __nv_bfloat16 g_kt[BB*HW*CC];   // k transposed: (b, m, c)
__device__ __align__(16) __nv_bfloat16 g_v [BB*CC*HW];   // v (b, c, s)
__device__ __align__(16) __nv_bfloat16 g_a [BB*HW*CC];   // attention out, (b, n, c)
__device__ __align__(16) __nv_bfloat16 g_wq[CC*CC], g_wk[CC*CC], g_wv[CC*CC], g_wp[CC*CC];

// ============================================================
// Weight conversion fp32 -> bf16 (once per launch, tiny)
// ============================================================
__global__ void wconv_kernel(const float* __restrict__ wq, const float* __restrict__ wk,
                             const float* __restrict__ wv, const float* __restrict__ wp) {
    int i = blockIdx.x * 256 + threadIdx.x;   // 65536 threads
    g_wq[i] = __float2bfloat16(wq[i]);
    g_wk[i] = __float2bfloat16(wk[i]);
    g_wv[i] = __float2bfloat16(wv[i]);
    g_wp[i] = __float2bfloat16(wp[i]);
}

// ============================================================
// GroupNorm: one block per (batch, group). bf16 output.
// ============================================================
__global__ void gn_kernel(const float* __restrict__ x,
                          const float* __restrict__ gw,
                          const float* __restrict__ gb) {
    int b = blockIdx.x >> 5;
    int g = blockIdx.x & 31;
    const float* xp = x   + ((size_t)b*CC + g*8) * HW;
    __nv_bfloat16* hp = g_h + ((size_t)b*CC + g*8) * HW;
    int tid = threadIdx.x;

    float s = 0.f, ss = 0.f;
    for (int i = tid; i < 8*HW; i += 256) {
        float v = xp[i];
        s += v; ss += v*v;
    }
    __shared__ float red0[8], red1[8];
    #pragma unroll
    for (int off = 16; off; off >>= 1) {
        s  += __shfl_xor_sync(0xffffffffu, s,  off);
        ss += __shfl_xor_sync(0xffffffffu, ss, off);
    }
    if ((tid & 31) == 0) { red0[tid>>5] = s; red1[tid>>5] = ss; }
    __syncthreads();
    __shared__ float mu_s, rstd_s;
    if (tid == 0) {
        float S = 0.f, SS = 0.f;
        #pragma unroll
        for (int i = 0; i < 8; i++) { S += red0[i]; SS += red1[i]; }
        float inv = 1.0f / (8.0f*HW);
        float mu = S * inv;
        float var = SS * inv - mu*mu;
        mu_s = mu;
        rstd_s = rsqrtf(var + 1e-5f);
    }
    __syncthreads();
    float mu = mu_s, rstd = rstd_s;
    for (int i = tid*2; i < 8*HW; i += 512) {
        int c = g*8 + (i >> 12);
        float a = gw[c]*rstd, bb2 = gb[c] - mu*a;
        float2 v = *reinterpret_cast<const float2*>(&xp[i]);
        __nv_bfloat162 r = __floats2bfloat162_rn(v.x*a + bb2, v.y*a + bb2);
        *reinterpret_cast<__nv_bfloat162*>(&hp[i]) = r;
    }
}

// ============================================================
// mma helpers
// ============================================================
__device__ __forceinline__ uint32_t s2u(const void* p) {
    uint32_t a;
    asm("{ .reg .u64 t; cvta.to.shared.u64 t, %1; cvt.u32.u64 %0, t; }" : "=r"(a) : "l"(p));
    return a;
}
__device__ __forceinline__ void ldm4(uint32_t& r0, uint32_t& r1, uint32_t& r2, uint32_t& r3, uint32_t a) {
    asm volatile("ldmatrix.sync.aligned.m8n8.x4.shared.b16 {%0,%1,%2,%3},[%4];"
                 : "=r"(r0), "=r"(r1), "=r"(r2), "=r"(r3) : "r"(a));
}
__device__ __forceinline__ void ldm4t(uint32_t& r0, uint32_t& r1, uint32_t& r2, uint32_t& r3, uint32_t a) {
    asm volatile("ldmatrix.sync.aligned.m8n8.x4.trans.shared.b16 {%0,%1,%2,%3},[%4];"
                 : "=r"(r0), "=r"(r1), "=r"(r2), "=r"(r3) : "r"(a));
}
__device__ __forceinline__ void mma16816(float* d, uint32_t a0, uint32_t a1, uint32_t a2, uint32_t a3,
                                         uint32_t b0, uint32_t b1) {
    asm volatile("mma.sync.aligned.m16n8k16.row.col.f32.bf16.bf16.f32 "
                 "{%0,%1,%2,%3},{%4,%5,%6,%7},{%8,%9},{%0,%1,%2,%3};"
                 : "+f"(d[0]), "+f"(d[1]), "+f"(d[2]), "+f"(d[3])
                 : "r"(a0), "r"(a1), "r"(a2), "r"(a3), "r"(b0), "r"(b1));
}
__device__ __forceinline__ uint32_t cvt2(float hi, float lo) {
    uint32_t d; asm("cvt.rn.bf16x2.f32 %0, %1, %2;" : "=r"(d) : "f"(hi), "f"(lo)); return d;
}
__device__ __forceinline__ void cpa16(uint32_t dst, const void* src) {
    asm volatile("cp.async.cg.shared.global [%0], [%1], 16;" :: "r"(dst), "l"(src));
}

// ============================================================
// 1x1 conv projections, bf16 tensor-core GEMM, full K=256 in smem.
// MODE 0: q  out[o,s]  (scaled 1/16)    M=o(64) N=s(128)
// MODE 1: kt out[s,o]                    M=s(128) N=o(64)
// MODE 2: v  out[o,s]                    M=o(64) N=s(128)
// grid: (32 s-blocks, 4 o-blocks, batch)
// ============================================================
#define HSTR 136   // H smem: 256 k-rows x 128 s-cols (+pad)
#define WSTR 264   // W smem: 64 o-rows x 256 k-cols (+pad)

template<int MODE>
__global__ void __launch_bounds__(256) proj_tc_kernel(const float* __restrict__ bias) {
    int b  = blockIdx.z;
    int s0 = blockIdx.x << 7;
    int o0 = blockIdx.y << 6;
    const __nv_bfloat16* Hb = g_h + (size_t)b*CC*HW;
    const __nv_bfloat16* Wb = (MODE == 0) ? g_wq : (MODE == 1) ? g_wk : g_wv;

    extern __shared__ __nv_bfloat16 smp[];
    __nv_bfloat16* Hs = smp;              // 256 x HSTR
    __nv_bfloat16* Ws = smp + 256*HSTR;   // 64 x WSTR

    int tid = threadIdx.x, lane = tid & 31, warp = tid >> 5;
    int l8 = lane & 7;

    // load H strip (256 x 128) and W block (64 x 256)
    for (int l = tid; l < 4096; l += 256) {
        int row = l >> 4, col = (l & 15) << 3;
        *reinterpret_cast<uint4*>(&Hs[row*HSTR + col]) =
            *reinterpret_cast<const uint4*>(&Hb[(size_t)row*HW + s0 + col]);
    }
    for (int l = tid; l < 2048; l += 256) {
        int row = l >> 5, col = (l & 31) << 3;
        *reinterpret_cast<uint4*>(&Ws[row*WSTR + col]) =
            *reinterpret_cast<const uint4*>(&Wb[(o0+row)*CC + col]);
    }
    __syncthreads();

    uint32_t Hsa = s2u(Hs), Wsa = s2u(Ws);
    float acc[8][4];
    #pragma unroll
    for (int j = 0; j < 8; j++) { acc[j][0]=acc[j][1]=acc[j][2]=acc[j][3]=0.f; }

    if (MODE != 1) {
        // M=o: A=W (non-trans), B=H (trans). warp: 16o x 64s
        int warp_o = warp >> 1, warp_s = warp & 1;
        uint32_t a_base = Wsa + (uint32_t)((warp_o*16 + l8 + ((lane>>3)&1)*8)*WSTR + (lane>>4)*8) * 2;
        uint32_t b_base = Hsa + (uint32_t)((l8 + ((lane>>3)&1)*8)*HSTR + warp_s*64 + (lane>>4)*8) * 2;
        #pragma unroll 4
        for (int kk = 0; kk < 16; kk++) {
            uint32_t a0,a1,a2,a3;
            ldm4(a0,a1,a2,a3, a_base + kk*32);
            #pragma unroll
            for (int g = 0; g < 4; g++) {
                uint32_t b00,b01,b10,b11;
                ldm4t(b00,b01,b10,b11, b_base + (uint32_t)(kk*16*HSTR + g*16)*2);
                mma16816(acc[2*g],   a0,a1,a2,a3, b00,b01);
                mma16816(acc[2*g+1], a0,a1,a2,a3, b10,b11);
            }
        }
        // epilogue: out[o, s]
        const float scale = (MODE == 0) ? 0.0625f : 1.0f;
        __nv_bfloat16* ob = (MODE == 0 ? g_q : g_v) + (size_t)b*CC*HW;
        int qr = lane >> 2, qc = (lane & 3) << 1;
        #pragma unroll
        for (int h = 0; h < 2; h++) {
            int o_r = o0 + warp_o*16 + qr + 8*h;
            float bv = bias[o_r];
            #pragma unroll
            for (int j = 0; j < 8; j++) {
                int s_c = s0 + warp_s*64 + j*8 + qc;
                uint32_t r = cvt2((acc[j][2*h+1]+bv)*scale, (acc[j][2*h]+bv)*scale);
                *reinterpret_cast<uint32_t*>(&ob[(size_t)o_r*HW + s_c]) = r;
            }
        }
    } else {
        // M=s: A=H (trans-A), B=W (non-trans). warp: 16s x 64o
        uint32_t a_base = Hsa + (uint32_t)((l8 + ((lane>>4)&1)*8)*HSTR + warp*16 + ((lane>>3)&1)*8) * 2;
        uint32_t b_base = Wsa + (uint32_t)((((lane>>4)&1)*8 + l8)*WSTR + ((lane>>3)&1)*8) * 2;
        #pragma unroll 4
        for (int kk = 0; kk < 16; kk++) {
            uint32_t a0,a1,a2,a3;
            ldm4t(a0,a1,a2,a3, a_base + (uint32_t)(kk*16*HSTR)*2);
            #pragma unroll
            for (int g = 0; g < 4; g++) {
                uint32_t b00,b01,b10,b11;
                ldm4(b00,b01,b10,b11, b_base + (uint32_t)(g*16*WSTR)*2 + kk*32);
                mma16816(acc[2*g],   a0,a1,a2,a3, b00,b01);
                mma16816(acc[2*g+1], a0,a1,a2,a3, b10,b11);
            }
        }
        // epilogue: out[s, o]
        __nv_bfloat16* ob = g_kt + (size_t)b*HW*CC;
        int qr = lane >> 2, qc = (lane & 3) << 1;
        #pragma unroll
        for (int h = 0; h < 2; h++) {
            int s_r = s0 + warp*16 + qr + 8*h;
            #pragma unroll
            for (int j = 0; j < 8; j++) {
                int o_c = o0 + j*8 + qc;
                uint32_t r = cvt2(acc[j][2*h+1]+bias[o_c+1], acc[j][2*h]+bias[o_c]);
                *reinterpret_cast<uint32_t*>(&ob[(size_t)s_r*CC + o_c]) = r;
            }
        }
    }
}

// ============================================================
// Flash attention, bf16 mma.sync, cp.async double-buffered K/V.
// 256 threads = 8 warps. Br=128, Bc=64, d=256.
// ============================================================
#define ASTR 264

__global__ void __launch_bounds__(256, 1) attn_kernel() {
    int b  = blockIdx.y;
    int n0 = blockIdx.x << 7;
    const __nv_bfloat16* qf = g_q  + (size_t)b*CC*HW;
    const __nv_bfloat16* kf = g_kt + (size_t)b*HW*CC;
    const __nv_bfloat16* vf = g_v  + (size_t)b*CC*HW;

    extern __shared__ __nv_bfloat16 sm[];
    __nv_bfloat16* Qs = sm;                         // 128 x ASTR
    __nv_bfloat16* Kb[2] = { Qs + 128*ASTR, Qs + 192*ASTR };
    __nv_bfloat16* Vb[2] = { Qs + 256*ASTR, Qs + 320*ASTR };

    int tid  = threadIdx.x;
    int lane = tid & 31, warp = tid >> 5;
    int r0 = warp << 4;
    int l8 = lane & 7;

    // load Q tile
    {
        const uint4* src = reinterpret_cast<const uint4*>(qf + (size_t)n0*CC);
        for (int l = tid; l < 4096; l += 256) {
            int row = l >> 5, col = (l & 31) << 3;
            *reinterpret_cast<uint4*>(&Qs[row*ASTR + col]) = src[l];
        }
    }

    // prefetch tile 0 via cp.async
    {
        uint32_t Kd = s2u(Kb[0]), Vd = s2u(Vb[0]);
        const uint4* ks = reinterpret_cast<const uint4*>(kf);
        const uint4* vs = reinterpret_cast<const uint4*>(vf);
        for (int l = tid; l < 2048; l += 256) {
            int row = l >> 5; uint32_t off = ((row*ASTR) + ((l & 31) << 3)) * 2;
            cpa16(Kd + off, &ks[l]);
            cpa16(Vd + off, &vs[l]);
        }
        asm volatile("cp.async.commit_group;");
    }

    uint32_t Qsa = s2u(Qs);
    uint32_t a_base = Qsa + ((r0 + l8 + ((lane >> 3) & 1)*8)*ASTR + (lane >> 4)*8) * 2;
    uint32_t kb_pat = (uint32_t)((((lane >> 4) & 1)*8 + l8)*ASTR + ((lane >> 3) & 1)*8) * 2;
    uint32_t vb_pat = (uint32_t)((((lane >> 3) & 1)*8 + l8)*ASTR + (lane >> 4)*8) * 2;

    float s[8][4];
    float o[32][4];
    #pragma unroll
    for (int j = 0; j < 32; j++) { o[j][0]=o[j][1]=o[j][2]=o[j][3]=0.f; }
    float mrow[2] = {-1e30f, -1e30f};
    float lrow[2] = {0.f, 0.f};

    for (int t = 0; t < 64; t++) {
        // prefetch next tile into other buffer (safe: prev compute on it done + barrier)
        if (t + 1 < 64) {
            int nb = (t + 1) & 1;
            uint32_t Kd = s2u(Kb[nb]), Vd = s2u(Vb[nb]);
            const uint4* ks = reinterpret_cast<const uint4*>(kf + (size_t)(t+1)*64*CC);
            const uint4* vs = reinterpret_cast<const uint4*>(vf + (size_t)(t+1)*64*CC);
            for (int l = tid; l < 2048; l += 256) {
                int row = l >> 5; uint32_t off = ((row*ASTR) + ((l & 31) << 3)) * 2;
                cpa16(Kd + off, &ks[l]);
                cpa16(Vd + off, &vs[l]);
            }
            asm volatile("cp.async.commit_group;");
            asm volatile("cp.async.wait_group 1;");
        } else {
            asm volatile("cp.async.wait_group 0;");
        }
        __syncthreads();

        uint32_t Ksa = s2u(Kb[t & 1]), Vsa = s2u(Vb[t & 1]);
        uint32_t kb_base = Ksa + kb_pat;
        uint32_t vb_base = Vsa + vb_pat;

        // ---- S = Q @ K^T ----
        #pragma unroll
        for (int j = 0; j < 8; j++) { s[j][0]=s[j][1]=s[j][2]=s[j][3]=0.f; }
        #pragma unroll 4
        for (int kk = 0; kk < 16; kk++) {
            uint32_t a0,a1,a2,a3;
            ldm4(a0,a1,a2,a3, a_base + kk*32);
            #pragma unroll
            for (int g = 0; g < 4; g++) {
                uint32_t b00,b01,b10,b11;
                ldm4(b00,b01,b10,b11, kb_base + (uint32_t)(g*16*ASTR)*2 + kk*32);
                mma16816(s[2*g],   a0,a1,a2,a3, b00,b01);
                mma16816(s[2*g+1], a0,a1,a2,a3, b10,b11);
            }
        }

        // ---- online softmax ----
        float alpha[2];
        #pragma unroll
        for (int h = 0; h < 2; h++) {
            float mx = -1e30f;
            #pragma unroll
            for (int j = 0; j < 8; j++) mx = fmaxf(mx, fmaxf(s[j][2*h], s[j][2*h+1]));
            mx = fmaxf(mx, __shfl_xor_sync(0xffffffffu, mx, 1));
            mx = fmaxf(mx, __shfl_xor_sync(0xffffffffu, mx, 2));
            float mn = fmaxf(mrow[h], mx);
            float al = __expf(mrow[h] - mn);
            mrow[h] = mn;
            float rs = 0.f;
            #pragma unroll
            for (int j = 0; j < 8; j++) {
                float p0 = __expf(s[j][2*h]   - mn);
                float p1 = __expf(s[j][2*h+1] - mn);
                s[j][2*h] = p0; s[j][2*h+1] = p1;
                rs += p0 + p1;
            }
            rs += __shfl_xor_sync(0xffffffffu, rs, 1);
            rs += __shfl_xor_sync(0xffffffffu, rs, 2);
            lrow[h] = lrow[h]*al + rs;
            alpha[h] = al;
        }
        #pragma unroll
        for (int j = 0; j < 32; j++) {
            o[j][0] *= alpha[0]; o[j][1] *= alpha[0];
            o[j][2] *= alpha[1]; o[j][3] *= alpha[1];
        }

        // ---- O += P @ V ----
        #pragma unroll
        for (int ks2 = 0; ks2 < 4; ks2++) {
            uint32_t a0 = cvt2(s[2*ks2][1],   s[2*ks2][0]);
            uint32_t a1 = cvt2(s[2*ks2][3],   s[2*ks2][2]);
            uint32_t a2 = cvt2(s[2*ks2+1][1], s[2*ks2+1][0]);
            uint32_t a3 = cvt2(s[2*ks2+1][3], s[2*ks2+1][2]);
            #pragma unroll
            for (int g = 0; g < 16; g++) {
                uint32_t b00,b01,b10,b11;
                ldm4t(b00,b01,b10,b11, vb_base + (uint32_t)(ks2*16*ASTR + g*16)*2);
                mma16816(o[2*g],   a0,a1,a2,a3, b00,b01);
                mma16816(o[2*g+1], a0,a1,a2,a3, b10,b11);
            }
        }
        __syncthreads();
    }

    // ---- epilogue: normalize, write g_a (n, c) bf16 ----
    __nv_bfloat16* ab = g_a + (size_t)b*HW*CC;
    int qr = lane >> 2, qc = (lane & 3) << 1;
    #pragma unroll
    for (int h = 0; h < 2; h++) {
        float inv = 1.0f / lrow[h];
        int row = n0 + r0 + qr + 8*h;
        #pragma unroll
        for (int j = 0; j < 32; j++) {
            uint32_t r = cvt2(o[j][2*h+1]*inv, o[j][2*h]*inv);
            *reinterpret_cast<uint32_t*>(&ab[(size_t)row*CC + 8*j + qc]) = r;
        }
    }
}

// ============================================================
// Output projection + residual, bf16 tensor-core GEMM, fp32 out:
// out[b,o,s] = x[b,o,s] + bp[o] + sum_c wp[o,c] * A[b,s,c]
// M=o(64), N=s(128): A=W non-trans, B=Astrip non-trans.
// ============================================================
#define PSTR2 264

__global__ void __launch_bounds__(256) outproj_tc_kernel(const float* __restrict__ bias,
                                                         const float* __restrict__ x,
                                                         float* __restrict__ outp) {
    int b  = blockIdx.z;
    int s0 = blockIdx.x << 7;
    int o0 = blockIdx.y << 6;
    const __nv_bfloat16* Ab = g_a + (size_t)b*HW*CC;

    extern __shared__ __nv_bfloat16 smp[];
    __nv_bfloat16* As = smp;               // 128 x PSTR2 (s rows, c cols)
    __nv_bfloat16* Ws = smp + 128*PSTR2;   // 64 x WSTR

    int tid = threadIdx.x, lane = tid & 31, warp = tid >> 5;
    int l8 = lane & 7;

    for (int l = tid; l < 4096; l += 256) {
        int row = l >> 5, col = (l & 31) << 3;
        *reinterpret_cast<uint4*>(&As[row*PSTR2 + col]) =
            *reinterpret_cast<const uint4*>(&Ab[(size_t)(s0+row)*CC + col]);
    }
    for (int l = tid; l < 2048; l += 256) {
        int row = l >> 5, col = (l & 31) << 3;
        *reinterpret_cast<uint4*>(&Ws[row*WSTR + col]) =
            *reinterpret_cast<const uint4*>(&g_wp[(o0+row)*CC + col]);
    }
    __syncthreads();

    uint32_t Asa = s2u(As), Wsa = s2u(Ws);
    int warp_o = warp >> 1, warp_s = warp & 1;
    uint32_t a_base = Wsa + (uint32_t)((warp_o*16 + l8 + ((lane>>3)&1)*8)*WSTR + (lane>>4)*8) * 2;
    uint32_t b_base = Asa + (uint32_t)((warp_s*64 + ((lane>>4)&1)*8 + l8)*PSTR2 + ((lane>>3)&1)*8) * 2;

    float acc[8][4];
    #pragma unroll
    for (int j = 0; j < 8; j++) { acc[j][0]=acc[j][1]=acc[j][2]=acc[j][3]=0.f; }

    #pragma unroll 4
    for (int kk = 0; kk < 16; kk++) {
        uint32_t a0,a1,a2,a3;
        ldm4(a0,a1,a2,a3, a_base + kk*32);
        #pragma unroll
        for (int g = 0; g < 4; g++) {
            uint32_t b00,b01,b10,b11;
            ldm4(b00,b01,b10,b11, b_base + (uint32_t)(g*16*PSTR2)*2 + kk*32);
            mma16816(acc[2*g],   a0,a1,a2,a3, b00,b01);
            mma16816(acc[2*g+1], a0,a1,a2,a3, b10,b11);
        }
    }

    const float* xb = x + (size_t)b*CC*HW;
    float* ob = outp + (size_t)b*CC*HW;
    int qr = lane >> 2, qc = (lane & 3) << 1;
    #pragma unroll
    for (int h = 0; h < 2; h++) {
        int o_r = o0 + warp_o*16 + qr + 8*h;
        float bv = bias[o_r];
        #pragma unroll
        for (int j = 0; j < 8; j++) {
            int s_c = s0 + warp_s*64 + j*8 + qc;
            size_t idx = (size_t)o_r*HW + s_c;
            float2 xv = *reinterpret_cast<const float2*>(&xb[idx]);
            float2 r = make_float2(acc[j][2*h] + bv + xv.x, acc[j][2*h+1] + bv + xv.y);
            *reinterpret_cast<float2*>(&ob[idx]) = r;
        }
    }
}

// ============================================================
extern "C" void kernel_launch(void* const* d_in, const int* in_sizes, int n_in,
                              void* d_out, int out_size) {
    const float* x    = (const float*)d_in[0];
    const float* gn_w = (const float*)d_in[1];
    const float* gn_b = (const float*)d_in[2];
    const float* wq   = (const float*)d_in[3];
    const float* bq   = (const float*)d_in[4];
    const float* wk   = (const float*)d_in[5];
    const float* bk   = (const float*)d_in[6];
    const float* wv   = (const float*)d_in[7];
    const float* bv   = (const float*)d_in[8];
    const float* wp   = (const float*)d_in[9];
    const float* bp   = (const float*)d_in[10];
    float* out = (float*)d_out;

    const int attn_smem = (128 + 4*64) * ASTR * 2;            // 202,752 B
    const int proj_smem = (256*HSTR + 64*WSTR) * 2;           // 103,424 B
    const int outp_smem = (128*PSTR2 + 64*WSTR) * 2;          // 101,376 B
    cudaFuncSetAttribute(attn_kernel, cudaFuncAttributeMaxDynamicSharedMemorySize, attn_smem);
    cudaFuncSetAttribute(proj_tc_kernel<0>, cudaFuncAttributeMaxDynamicSharedMemorySize, proj_smem);
    cudaFuncSetAttribute(proj_tc_kernel<1>, cudaFuncAttributeMaxDynamicSharedMemorySize, proj_smem);
    cudaFuncSetAttribute(proj_tc_kernel<2>, cudaFuncAttributeMaxDynamicSharedMemorySize, proj_smem);
    cudaFuncSetAttribute(outproj_tc_kernel, cudaFuncAttributeMaxDynamicSharedMemorySize, outp_smem);

    wconv_kernel<<<256, 256>>>(wq, wk, wv, wp);
    gn_kernel<<<128, 256>>>(x, gn_w, gn_b);

    dim3 pg(32, 4, BB);
    proj_tc_kernel<0><<<pg, 256, proj_smem>>>(bq);
    proj_tc_kernel<1><<<pg, 256, proj_smem>>>(bk);
    proj_tc_kernel<2><<<pg, 256, proj_smem>>>(bv);

    dim3 ag(32, BB);
    attn_kernel<<<ag, 256, attn_smem>>>();

    outproj_tc_kernel<<<pg, 256, outp_smem>>>(bp, x, out);
}